// round 11
// baseline (speedup 1.0000x reference)
#include <cuda_runtime.h>
#include <cuda_fp16.h>
#include <math.h>
#include <stdint.h>

#define BB 8
#define SS 4096
#define DD 256
#define HH 64
#define RT (BB*SS)
#define TQ 64          // q rows per CTA
#define TK 256         // keys per tile
#define NT (SS/TK)     // 16 tiles
#define CAP 16

// ---------------- scratch ----------------
__device__ float g_Qf[RT*HH];
__device__ float g_Kf[RT*HH];
__device__ float g_Vf[RT*HH];
__device__ __half g_Kh[RT*HH];
__device__ float g_gate[BB*HH];

__device__ __forceinline__ unsigned fkey(float f) {
    unsigned u = __float_as_uint(f);
    return u ^ ((unsigned)((int)u >> 31) | 0x80000000u);
}
__device__ __forceinline__ float funkey(unsigned u) {
    u ^= (u & 0x80000000u) ? 0x80000000u : 0xffffffffu;
    return __uint_as_float(u);
}

#define CP16(dst, src)  asm volatile("cp.async.cg.shared.global [%0], [%1], 16;" :: "r"(dst), "l"(src) : "memory")
#define CP_COMMIT()     asm volatile("cp.async.commit_group;" ::: "memory")
#define CP_WAIT0()      asm volatile("cp.async.wait_group 0;" ::: "memory")
#define CP_WAIT1()      asm volatile("cp.async.wait_group 1;" ::: "memory")

__device__ __forceinline__ uint32_t smem_u32(const void* p) {
    uint32_t a;
    asm("{ .reg .u64 t; cvta.to.shared.u64 t, %1; cvt.u32.u64 %0, t; }" : "=r"(a) : "l"(p));
    return a;
}

// ---------------- kernel 1: fused QKV GEMM ----------------
__global__ __launch_bounds__(192) void qkv_kernel(
    const float* __restrict__ x, const float* __restrict__ Wq,
    const float* __restrict__ Wk, const float* __restrict__ Wv)
{
    __shared__ float xs[32][DD];
    int row0 = blockIdx.x * 32;
    int tid = threadIdx.x;
    for (int idx = tid; idx < 32*DD; idx += 192) {
        int r = idx >> 8, k = idx & 255;
        xs[r][k] = x[(size_t)(row0 + r)*DD + k];
    }
    __syncthreads();

    int m = tid >> 6;
    int h = tid & 63;
    const float* W = (m == 0) ? Wq : (m == 1) ? Wk : Wv;
    float* O = (m == 0) ? g_Qf : (m == 1) ? g_Kf : g_Vf;

    float acc[32];
    #pragma unroll
    for (int r = 0; r < 32; r++) acc[r] = 0.f;

    #pragma unroll 4
    for (int k = 0; k < DD; k += 2) {
        float w0 = W[(k+0)*HH + h];
        float w1 = W[(k+1)*HH + h];
        #pragma unroll
        for (int r = 0; r < 32; r++) {
            float2 a = *(const float2*)&xs[r][k];
            acc[r] = fmaf(a.x, w0, fmaf(a.y, w1, acc[r]));
        }
    }
    #pragma unroll
    for (int r = 0; r < 32; r++) {
        float v = acc[r];
        O[(size_t)(row0 + r)*HH + h] = v;
        if (m == 1) g_Kh[(size_t)(row0 + r)*HH + h] = __float2half(v);
    }
}

// ---------------- kernel 2: gate ----------------
__global__ __launch_bounds__(128) void gate_kernel() {
    int b = blockIdx.x >> 6;
    int h = blockIdx.x & 63;
    float s = 0.f;
    for (int i = threadIdx.x; i < SS; i += 128)
        s += g_Qf[((size_t)b*SS + i)*HH + h];
    __shared__ float red[128];
    red[threadIdx.x] = s;
    __syncthreads();
    for (int off = 64; off; off >>= 1) {
        if (threadIdx.x < off) red[threadIdx.x] += red[threadIdx.x + off];
        __syncthreads();
    }
    if (threadIdx.x == 0)
        g_gate[blockIdx.x] = 1.f / (1.f + expf(-red[0] * (1.f / (float)SS)));
}

// ---------------- kernel 3: two-sweep attention (f16-acc screen) ----------------
struct __align__(16) Smem {
    float Qs[64*64];                    // fp32 Q [row][d]  16384 B
    __half Kh[2][256*72];               // f16 K tiles      73728 B
    unsigned rowtile[64*NT];            // 4096 B
    float Mpre[64];
    float thrpre[64];
    unsigned thrkey[64];
    float cand_t[64*CAP];
    unsigned short cand_idx[64*CAP];
    unsigned cnt[64];
    int list[64];
    int nlist;
    int pad_;
    float so[8*64];
};

__global__ __launch_bounds__(256, 2) void attn_kernel(float* __restrict__ out) {
    extern __shared__ Smem smem[];
    Smem& S = smem[0];

    int tid = threadIdx.x;
    int b  = blockIdx.x >> 6;
    int q0 = (blockIdx.x & 63) * TQ;

    for (int i = tid; i < 64*NT; i += 256) S.rowtile[i] = 0u;

    // load Q fp32 row-major
    {
        int row = tid >> 2, qt = (tid & 3) * 16;
        const float* Qr = &g_Qf[((size_t)b*SS + q0 + row)*HH + qt];
        #pragma unroll
        for (int d4 = 0; d4 < 16; d4 += 4)
            *(float4*)&S.Qs[row*64 + qt + d4] = *(const float4*)&Qr[d4];
    }

    // preload K tile 0 (f16) into buf 0
    uint32_t kb_base = smem_u32(&S.Kh[0][0]);
    {
        const __half* Ksrc = &g_Kh[((size_t)b*SS)*HH];
        #pragma unroll
        for (int j = 0; j < 8; j++) {
            int ch = tid + j*256;
            int key = ch >> 3, cc = ch & 7;
            CP16(kb_base + key*144 + cc*16, (const void*)(Ksrc + (size_t)key*HH + cc*8));
        }
        CP_COMMIT();
    }
    __syncthreads();

    int warp = tid >> 5, lane = tid & 31;
    int g = lane >> 2, tg = lane & 3;
    int wm = warp >> 1, wn = warp & 1;

    // ---- A-fragments (f16) in registers, built once from fp32 Q ----
    uint32_t afr[4][4];
    {
        int r0 = wm*16 + g, r1 = r0 + 8;
        #pragma unroll
        for (int kki = 0; kki < 4; kki++) {
            int c0 = kki*16 + tg*2, c1 = c0 + 8;
            __half2 p;
            p = __floats2half2_rn(S.Qs[r0*64+c0], S.Qs[r0*64+c0+1]); afr[kki][0] = *(uint32_t*)&p;
            p = __floats2half2_rn(S.Qs[r1*64+c0], S.Qs[r1*64+c0+1]); afr[kki][1] = *(uint32_t*)&p;
            p = __floats2half2_rn(S.Qs[r0*64+c1], S.Qs[r0*64+c1+1]); afr[kki][2] = *(uint32_t*)&p;
            p = __floats2half2_rn(S.Qs[r1*64+c1], S.Qs[r1*64+c1+1]); afr[kki][3] = *(uint32_t*)&p;
        }
    }

    // ================= sweep 1: f16 mma (f16 accumulate), per-(row,tile) max ========
    int buf = 0;
    for (int kt = 0; kt < NT; kt++) {
        if (kt + 1 < NT) {
            const __half* Ksrc = &g_Kh[((size_t)b*SS + (kt+1)*TK)*HH];
            uint32_t kb = smem_u32(&S.Kh[buf ^ 1][0]);
            #pragma unroll
            for (int j = 0; j < 8; j++) {
                int ch = tid + j*256;
                int key = ch >> 3, cc = ch & 7;
                CP16(kb + key*144 + cc*16, (const void*)(Ksrc + (size_t)key*HH + cc*8));
            }
            CP_COMMIT();
            CP_WAIT1();
        } else {
            CP_WAIT0();
        }
        __syncthreads();   // K[buf] visible to all warps

        const __half* KB = &S.Kh[buf][0];
        uint32_t acc[16][2];
        #pragma unroll
        for (int ni = 0; ni < 16; ni++) { acc[ni][0] = 0u; acc[ni][1] = 0u; }

        #pragma unroll
        for (int kki = 0; kki < 4; kki++) {
            int kk = kki*16;
            #pragma unroll
            for (int ni = 0; ni < 16; ni++) {
                int key = wn*128 + ni*8 + g;
                uint32_t b0 = *(const uint32_t*)&KB[key*72 + kk + tg*2];
                uint32_t b1 = *(const uint32_t*)&KB[key*72 + kk + 8 + tg*2];
                asm volatile(
                    "mma.sync.aligned.m16n8k16.row.col.f16.f16.f16.f16 "
                    "{%0,%1}, {%2,%3,%4,%5}, {%6,%7}, {%0,%1};"
                    : "+r"(acc[ni][0]), "+r"(acc[ni][1])
                    : "r"(afr[kki][0]), "r"(afr[kki][1]), "r"(afr[kki][2]), "r"(afr[kki][3]),
                      "r"(b0), "r"(b1));
            }
        }

        // per-row max: acc[ni][0] = row wm*16+g (2 cols), acc[ni][1] = row +8
        __half2 mx0 = __float2half2_rn(-60000.f);
        __half2 mx1 = __float2half2_rn(-60000.f);
        #pragma unroll
        for (int ni = 0; ni < 16; ni++) {
            mx0 = __hmax2(mx0, *(__half2*)&acc[ni][0]);
            mx1 = __hmax2(mx1, *(__half2*)&acc[ni][1]);
        }
        float m0 = fmaxf(__low2float(mx0), __high2float(mx0));
        float m1 = fmaxf(__low2float(mx1), __high2float(mx1));
        m0 = fmaxf(m0, __shfl_xor_sync(0xffffffffu, m0, 1));
        m0 = fmaxf(m0, __shfl_xor_sync(0xffffffffu, m0, 2));
        m1 = fmaxf(m1, __shfl_xor_sync(0xffffffffu, m1, 1));
        m1 = fmaxf(m1, __shfl_xor_sync(0xffffffffu, m1, 2));
        if (tg == 0) {
            atomicMax(&S.rowtile[(wm*16 + g    )*NT + kt], fkey(m0));
            atomicMax(&S.rowtile[(wm*16 + g + 8)*NT + kt], fkey(m1));
        }
        __syncthreads();   // done reading K[buf] before refill
        buf ^= 1;
    }

    // thresholds (f16-acc error margins, pre-scale: ±~80 covered by 320/400)
    if (tid < 64) {
        unsigned mk = 0u;
        #pragma unroll
        for (int t = 0; t < NT; t++) mk = max(mk, S.rowtile[tid*NT + t]);
        float Mp = funkey(mk);
        S.Mpre[tid]   = Mp;
        S.thrpre[tid] = Mp - 320.f;
        S.thrkey[tid] = fkey(Mp - 400.f);
        S.cnt[tid] = (Mp < 400.f) ? (CAP + 1000u) : 0u;
    }
    __syncthreads();

    // ================= sweep 2: exact fp32 recompute on qualifying tiles =================
    for (int kt = 0; kt < NT; kt++) {
        if (tid == 0) S.nlist = 0;
        __syncthreads();
        if (tid < 64 && S.rowtile[tid*NT + kt] > S.thrkey[tid])
            S.list[atomicAdd(&S.nlist, 1)] = tid;
        __syncthreads();
        int n = S.nlist;
        if (n > 0) {
            float4 kr[16];
            const float* Kr = &g_Kf[((size_t)b*SS + kt*TK + tid)*HH];
            #pragma unroll
            for (int i = 0; i < 16; i++) kr[i] = *(const float4*)&Kr[i*4];
            for (int j = 0; j < n; j++) {
                int row = S.list[j];
                const float* Q = &S.Qs[row*64];
                float s0 = 0.f, s1 = 0.f, s2 = 0.f, s3 = 0.f;
                #pragma unroll
                for (int i = 0; i < 16; i++) {
                    s0 = fmaf(Q[i*4+0], kr[i].x, s0);
                    s1 = fmaf(Q[i*4+1], kr[i].y, s1);
                    s2 = fmaf(Q[i*4+2], kr[i].z, s2);
                    s3 = fmaf(Q[i*4+3], kr[i].w, s3);
                }
                float spre = (s0 + s1) + (s2 + s3);
                if (spre > S.thrpre[row]) {
                    float sc = spre * 0.125f;
                    float t = (sc > 0.f) ? sc : expm1f(sc);
                    unsigned slot = atomicAdd(&S.cnt[row], 1u);
                    if (slot < CAP) {
                        S.cand_t[row*CAP + slot] = t;
                        S.cand_idx[row*CAP + slot] = (unsigned short)(kt*TK + tid);
                    }
                }
            }
        }
        __syncthreads();
    }

    // ================= epilogue: detect + softmax + PV + gate =================
    for (int rr = 0; rr < 8; rr++) {
        int row = warp*8 + rr;
        unsigned c = S.cnt[row];
        bool bad = (c > CAP) || (c == 0);
        float l = 0.f;
        float2 o = make_float2(0.f, 0.f);

        if (!bad) {
            float M = -3e38f;
            for (unsigned k = 0; k < c; k++) M = fmaxf(M, S.cand_t[row*CAP + k]);
            if (M < S.Mpre[row]*0.125f - 16.f) bad = true;   // consistency check
            if (!bad) {
                for (unsigned k = 0; k < c; k++) {
                    float w = __expf(S.cand_t[row*CAP + k] - M);
                    int idx = S.cand_idx[row*CAP + k];
                    float2 v = *(const float2*)&g_Vf[((size_t)b*SS + idx)*HH + lane*2];
                    l += w;
                    o.x += w * v.x;
                    o.y += w * v.y;
                }
            }
        }

        if (bad) {
            // ---- exact full-row fallback ----
            const float* Q = &S.Qs[row*64];
            float fm = -3e38f, fl = 0.f;
            for (int k = lane; k < SS; k += 32) {
                const float* Kr = &g_Kf[((size_t)b*SS + k)*HH];
                float s = 0.f;
                #pragma unroll 16
                for (int d = 0; d < HH; d++) s = fmaf(Q[d], Kr[d], s);
                s *= 0.125f;
                float t = (s > 0.f) ? s : expm1f(s);
                float mn = fmaxf(fm, t);
                fl = fl*__expf(fm - mn) + __expf(t - mn);
                fm = mn;
            }
            #pragma unroll
            for (int off = 16; off; off >>= 1) {
                float om = __shfl_xor_sync(0xffffffffu, fm, off);
                float ol = __shfl_xor_sync(0xffffffffu, fl, off);
                float mn = fmaxf(fm, om);
                fl = fl*__expf(fm - mn) + ol*__expf(om - mn);
                fm = mn;
            }
            S.so[warp*64 + lane] = 0.f;
            S.so[warp*64 + lane + 32] = 0.f;
            __syncwarp();
            for (int k = lane; k < SS; k += 32) {
                const float* Kr = &g_Kf[((size_t)b*SS + k)*HH];
                float s = 0.f;
                #pragma unroll 16
                for (int d = 0; d < HH; d++) s = fmaf(Q[d], Kr[d], s);
                s *= 0.125f;
                float t = (s > 0.f) ? s : expm1f(s);
                if (t > fm - 20.f) {
                    float w = __expf(t - fm);
                    const float* Vr = &g_Vf[((size_t)b*SS + k)*HH];
                    for (int h = 0; h < HH; h++)
                        atomicAdd(&S.so[warp*64 + h], w * Vr[h]);
                }
            }
            __syncwarp();
            l = fl;
            o.x = S.so[warp*64 + lane*2];
            o.y = S.so[warp*64 + lane*2 + 1];
        }

        float inv = (l > 0.f) ? (1.f / l) : 0.f;
        float2 gt = *(const float2*)&g_gate[b*HH + lane*2];
        float2 res = make_float2(o.x*inv*gt.x, o.y*inv*gt.y);
        *(float2*)&out[((size_t)b*SS + q0 + row)*HH + lane*2] = res;
    }
}

// ---------------- launch ----------------
extern "C" void kernel_launch(void* const* d_in, const int* in_sizes, int n_in,
                              void* d_out, int out_size) {
    int xi = 0;
    for (int i = 0; i < 4; i++) if (in_sizes[i] == BB*SS*DD) { xi = i; break; }
    const float* ptrs[3];
    int w = 0;
    for (int i = 0; i < 4; i++) if (i != xi) ptrs[w++] = (const float*)d_in[i];
    const float* x  = (const float*)d_in[xi];
    const float* Wq = ptrs[0];
    const float* Wk = ptrs[1];
    const float* Wv = ptrs[2];
    float* out = (float*)d_out;

    cudaFuncSetAttribute(attn_kernel, cudaFuncAttributeMaxDynamicSharedMemorySize,
                         (int)sizeof(Smem));

    qkv_kernel<<<RT/32, 192>>>(x, Wq, Wk, Wv);
    gate_kernel<<<BB*HH, 128>>>();
    attn_kernel<<<BB*(SS/TQ), 256, sizeof(Smem)>>>(out);
}

// round 13
// speedup vs baseline: 1.0982x; 1.0982x over previous
#include <cuda_runtime.h>
#include <cuda_bf16.h>
#include <cuda_fp16.h>
#include <math.h>
#include <stdint.h>

#define BB 8
#define SS 4096
#define DD 256
#define HH 64
#define RT (BB*SS)
#define TQ 64          // q rows per CTA (attn)
#define TK 256         // keys per tile
#define NT (SS/TK)     // 16 tiles
#define CAP 16

// ---------------- scratch ----------------
__device__ float g_Qf[RT*HH];
__device__ float g_Kf[RT*HH];
__device__ float g_Vf[RT*HH];
__device__ __nv_bfloat16 g_Kb[RT*HH];
__device__ float g_gate[BB*HH];

__device__ __forceinline__ unsigned fkey(float f) {
    unsigned u = __float_as_uint(f);
    return u ^ ((unsigned)((int)u >> 31) | 0x80000000u);
}
__device__ __forceinline__ float funkey(unsigned u) {
    u ^= (u & 0x80000000u) ? 0x80000000u : 0xffffffffu;
    return __uint_as_float(u);
}

#define PACK2(dst, x) asm("mov.b64 %0, {%1, %1};" : "=l"(dst) : "r"(__float_as_uint(x)))
#define FMA2(acc, a, b) asm("fma.rn.f32x2 %0, %1, %2, %0;" : "+l"(acc) : "l"(a), "l"(b))
#define UNPACK2(lo, hi, v) asm("mov.b64 {%0, %1}, %2;" : "=r"(lo), "=r"(hi) : "l"(v))

#define CP16(dst, src)  asm volatile("cp.async.cg.shared.global [%0], [%1], 16;" :: "r"(dst), "l"(src) : "memory")
#define CP_COMMIT()     asm volatile("cp.async.commit_group;" ::: "memory")
#define CP_WAIT0()      asm volatile("cp.async.wait_group 0;" ::: "memory")
#define CP_WAIT1()      asm volatile("cp.async.wait_group 1;" ::: "memory")

__device__ __forceinline__ uint32_t smem_u32(const void* p) {
    uint32_t a;
    asm("{ .reg .u64 t; cvta.to.shared.u64 t, %1; cvt.u32.u64 %0, t; }" : "=r"(a) : "l"(p));
    return a;
}

// ---------------- kernel 1: fused QKV GEMM (FMA2, LDS.128-lean) ----------------
// 192 threads: m(3) x h-quad(16) x rowgroup(4); 32 rows/block, 8 interleaved rows/thread
#define XSTR 260    // floats per x row in smem (260 mod 32 = 4 -> conflict-free rowgroups)
__global__ __launch_bounds__(192) void qkv_kernel(
    const float* __restrict__ x, const float* __restrict__ Wq,
    const float* __restrict__ Wk, const float* __restrict__ Wv)
{
    __shared__ __align__(16) float xs[32*XSTR];
    int row0 = blockIdx.x * 32;
    int tid = threadIdx.x;

    for (int idx = tid; idx < 32*64; idx += 192) {
        int r = idx >> 6, k4 = (idx & 63) << 2;
        *(float4*)&xs[r*XSTR + k4] = *(const float4*)&x[(size_t)(row0 + r)*DD + k4];
    }
    __syncthreads();

    int m  = tid / 64;          // 0:Q 1:K 2:V
    int hq = (tid & 63) >> 2;   // 0..15
    int rg = tid & 3;           // 0..3  (rows rg, rg+4, ..., rg+28)
    int h0 = hq * 4;
    const float* W = (m == 0) ? Wq : (m == 1) ? Wk : Wv;
    float* O = (m == 0) ? g_Qf : (m == 1) ? g_Kf : g_Vf;

    unsigned long long acc2[8][2];
    #pragma unroll
    for (int i = 0; i < 8; i++) { acc2[i][0] = 0ull; acc2[i][1] = 0ull; }

    #pragma unroll 2
    for (int k = 0; k < DD; k += 4) {
        ulonglong2 w[4];
        #pragma unroll
        for (int kk = 0; kk < 4; kk++)
            w[kk] = *(const ulonglong2*)&W[(size_t)(k+kk)*HH + h0];
        #pragma unroll
        for (int i = 0; i < 8; i++) {
            float4 xv = *(const float4*)&xs[(rg + 4*i)*XSTR + k];
            unsigned long long xp;
            PACK2(xp, xv.x); FMA2(acc2[i][0], w[0].x, xp); FMA2(acc2[i][1], w[0].y, xp);
            PACK2(xp, xv.y); FMA2(acc2[i][0], w[1].x, xp); FMA2(acc2[i][1], w[1].y, xp);
            PACK2(xp, xv.z); FMA2(acc2[i][0], w[2].x, xp); FMA2(acc2[i][1], w[2].y, xp);
            PACK2(xp, xv.w); FMA2(acc2[i][0], w[3].x, xp); FMA2(acc2[i][1], w[3].y, xp);
        }
    }

    #pragma unroll
    for (int i = 0; i < 8; i++) {
        int row = row0 + rg + 4*i;
        unsigned a, bq, cq, dq;
        UNPACK2(a, bq, acc2[i][0]);
        UNPACK2(cq, dq, acc2[i][1]);
        float4 o;
        o.x = __uint_as_float(a);  o.y = __uint_as_float(bq);
        o.z = __uint_as_float(cq); o.w = __uint_as_float(dq);
        *(float4*)&O[(size_t)row*HH + h0] = o;
        if (m == 1) {
            __nv_bfloat162 p0 = __floats2bfloat162_rn(o.x, o.y);
            __nv_bfloat162 p1 = __floats2bfloat162_rn(o.z, o.w);
            uint2 pk; pk.x = *(unsigned*)&p0; pk.y = *(unsigned*)&p1;
            *(uint2*)&g_Kb[(size_t)row*HH + h0] = pk;
        }
    }
}

// ---------------- kernel 2: gate ----------------
__global__ __launch_bounds__(128) void gate_kernel() {
    int b = blockIdx.x >> 6;
    int h = blockIdx.x & 63;
    float s = 0.f;
    for (int i = threadIdx.x; i < SS; i += 128)
        s += g_Qf[((size_t)b*SS + i)*HH + h];
    __shared__ float red[128];
    red[threadIdx.x] = s;
    __syncthreads();
    for (int off = 64; off; off >>= 1) {
        if (threadIdx.x < off) red[threadIdx.x] += red[threadIdx.x + off];
        __syncthreads();
    }
    if (threadIdx.x == 0)
        g_gate[blockIdx.x] = 1.f / (1.f + expf(-red[0] * (1.f / (float)SS)));
}

// ---------------- kernel 3: two-sweep attention (validated round-10 version) ------
struct __align__(16) Smem {
    float Qs[64*64];
    __nv_bfloat16 Kb[2][256*72];
    unsigned rowtile[64*NT];
    float Mpre[64];
    float thrpre[64];
    unsigned thrkey[64];
    float cand_t[64*CAP];
    unsigned short cand_idx[64*CAP];
    unsigned cnt[64];
    int list[64];
    int nlist;
    int pad_;
    float so[8*64];
};

__global__ __launch_bounds__(256, 2) void attn_kernel(float* __restrict__ out) {
    extern __shared__ Smem smem[];
    Smem& S = smem[0];

    int tid = threadIdx.x;
    int b  = blockIdx.x >> 6;
    int q0 = (blockIdx.x & 63) * TQ;

    for (int i = tid; i < 64*NT; i += 256) S.rowtile[i] = 0u;

    {
        int row = tid >> 2, qt = (tid & 3) * 16;
        const float* Qr = &g_Qf[((size_t)b*SS + q0 + row)*HH + qt];
        #pragma unroll
        for (int d4 = 0; d4 < 16; d4 += 4)
            *(float4*)&S.Qs[row*64 + qt + d4] = *(const float4*)&Qr[d4];
    }

    uint32_t kb_base = smem_u32(&S.Kb[0][0]);
    {
        const __nv_bfloat16* Ksrc = &g_Kb[((size_t)b*SS)*HH];
        #pragma unroll
        for (int j = 0; j < 8; j++) {
            int ch = tid + j*256;
            int key = ch >> 3, cc = ch & 7;
            CP16(kb_base + key*144 + cc*16, (const void*)(Ksrc + (size_t)key*HH + cc*8));
        }
        CP_COMMIT();
    }
    __syncthreads();

    int warp = tid >> 5, lane = tid & 31;
    int g = lane >> 2, tg = lane & 3;
    int wm = warp >> 1, wn = warp & 1;

    uint32_t afr[4][4];
    {
        int r0 = wm*16 + g, r1 = r0 + 8;
        #pragma unroll
        for (int kki = 0; kki < 4; kki++) {
            int c0 = kki*16 + tg*2, c1 = c0 + 8;
            __nv_bfloat162 p;
            p = __floats2bfloat162_rn(S.Qs[r0*64+c0], S.Qs[r0*64+c0+1]); afr[kki][0] = *(uint32_t*)&p;
            p = __floats2bfloat162_rn(S.Qs[r1*64+c0], S.Qs[r1*64+c0+1]); afr[kki][1] = *(uint32_t*)&p;
            p = __floats2bfloat162_rn(S.Qs[r0*64+c1], S.Qs[r0*64+c1+1]); afr[kki][2] = *(uint32_t*)&p;
            p = __floats2bfloat162_rn(S.Qs[r1*64+c1], S.Qs[r1*64+c1+1]); afr[kki][3] = *(uint32_t*)&p;
        }
    }

    int buf = 0;
    for (int kt = 0; kt < NT; kt++) {
        if (kt + 1 < NT) {
            const __nv_bfloat16* Ksrc = &g_Kb[((size_t)b*SS + (kt+1)*TK)*HH];
            uint32_t kb = smem_u32(&S.Kb[buf ^ 1][0]);
            #pragma unroll
            for (int j = 0; j < 8; j++) {
                int ch = tid + j*256;
                int key = ch >> 3, cc = ch & 7;
                CP16(kb + key*144 + cc*16, (const void*)(Ksrc + (size_t)key*HH + cc*8));
            }
            CP_COMMIT();
            CP_WAIT1();
        } else {
            CP_WAIT0();
        }
        __syncthreads();

        const __nv_bfloat16* KB = &S.Kb[buf][0];
        float acc[16][4];
        #pragma unroll
        for (int ni = 0; ni < 16; ni++)
            #pragma unroll
            for (int e = 0; e < 4; e++) acc[ni][e] = 0.f;

        #pragma unroll
        for (int kki = 0; kki < 4; kki++) {
            int kk = kki*16;
            #pragma unroll
            for (int ni = 0; ni < 16; ni++) {
                int key = wn*128 + ni*8 + g;
                uint32_t b0 = *(const uint32_t*)&KB[key*72 + kk + tg*2];
                uint32_t b1 = *(const uint32_t*)&KB[key*72 + kk + 8 + tg*2];
                asm volatile(
                    "mma.sync.aligned.m16n8k16.row.col.f32.bf16.bf16.f32 "
                    "{%0,%1,%2,%3}, {%4,%5,%6,%7}, {%8,%9}, {%0,%1,%2,%3};"
                    : "+f"(acc[ni][0]), "+f"(acc[ni][1]),
                      "+f"(acc[ni][2]), "+f"(acc[ni][3])
                    : "r"(afr[kki][0]), "r"(afr[kki][1]), "r"(afr[kki][2]), "r"(afr[kki][3]),
                      "r"(b0), "r"(b1));
            }
        }

        float m0 = -3e38f, m1 = -3e38f;
        #pragma unroll
        for (int ni = 0; ni < 16; ni++) {
            m0 = fmaxf(m0, fmaxf(acc[ni][0], acc[ni][1]));
            m1 = fmaxf(m1, fmaxf(acc[ni][2], acc[ni][3]));
        }
        m0 = fmaxf(m0, __shfl_xor_sync(0xffffffffu, m0, 1));
        m0 = fmaxf(m0, __shfl_xor_sync(0xffffffffu, m0, 2));
        m1 = fmaxf(m1, __shfl_xor_sync(0xffffffffu, m1, 1));
        m1 = fmaxf(m1, __shfl_xor_sync(0xffffffffu, m1, 2));
        if (tg == 0) {
            atomicMax(&S.rowtile[(wm*16 + g    )*NT + kt], fkey(m0));
            atomicMax(&S.rowtile[(wm*16 + g + 8)*NT + kt], fkey(m1));
        }
        __syncthreads();
        buf ^= 1;
    }

    if (tid < 64) {
        unsigned mk = 0u;
        #pragma unroll
        for (int t = 0; t < NT; t++) mk = max(mk, S.rowtile[tid*NT + t]);
        float Mp = funkey(mk);
        S.Mpre[tid]   = Mp;
        S.thrpre[tid] = Mp - 200.f;
        S.thrkey[tid] = fkey(Mp - 240.f);
        S.cnt[tid] = (Mp < 240.f) ? (CAP + 1000u) : 0u;
    }
    __syncthreads();

    for (int kt = 0; kt < NT; kt++) {
        if (tid == 0) S.nlist = 0;
        __syncthreads();
        if (tid < 64 && S.rowtile[tid*NT + kt] > S.thrkey[tid])
            S.list[atomicAdd(&S.nlist, 1)] = tid;
        __syncthreads();
        int n = S.nlist;
        if (n > 0) {
            float4 kr[16];
            const float* Kr = &g_Kf[((size_t)b*SS + kt*TK + tid)*HH];
            #pragma unroll
            for (int i = 0; i < 16; i++) kr[i] = *(const float4*)&Kr[i*4];
            for (int j = 0; j < n; j++) {
                int row = S.list[j];
                const float* Q = &S.Qs[row*64];
                float s0 = 0.f, s1 = 0.f, s2 = 0.f, s3 = 0.f;
                #pragma unroll
                for (int i = 0; i < 16; i++) {
                    s0 = fmaf(Q[i*4+0], kr[i].x, s0);
                    s1 = fmaf(Q[i*4+1], kr[i].y, s1);
                    s2 = fmaf(Q[i*4+2], kr[i].z, s2);
                    s3 = fmaf(Q[i*4+3], kr[i].w, s3);
                }
                float spre = (s0 + s1) + (s2 + s3);
                if (spre > S.thrpre[row]) {
                    float sc = spre * 0.125f;
                    float t = (sc > 0.f) ? sc : expm1f(sc);
                    unsigned slot = atomicAdd(&S.cnt[row], 1u);
                    if (slot < CAP) {
                        S.cand_t[row*CAP + slot] = t;
                        S.cand_idx[row*CAP + slot] = (unsigned short)(kt*TK + tid);
                    }
                }
            }
        }
        __syncthreads();
    }

    for (int rr = 0; rr < 8; rr++) {
        int row = warp*8 + rr;
        unsigned c = S.cnt[row];
        bool bad = (c > CAP) || (c == 0);
        float l = 0.f;
        float2 o = make_float2(0.f, 0.f);

        if (!bad) {
            float M = -3e38f;
            for (unsigned k = 0; k < c; k++) M = fmaxf(M, S.cand_t[row*CAP + k]);
            if (M < S.Mpre[row]*0.125f - 6.f) bad = true;
            if (!bad) {
                for (unsigned k = 0; k < c; k++) {
                    float w = __expf(S.cand_t[row*CAP + k] - M);
                    int idx = S.cand_idx[row*CAP + k];
                    float2 v = *(const float2*)&g_Vf[((size_t)b*SS + idx)*HH + lane*2];
                    l += w;
                    o.x += w * v.x;
                    o.y += w * v.y;
                }
            }
        }

        if (bad) {
            const float* Q = &S.Qs[row*64];
            float fm = -3e38f, fl = 0.f;
            for (int k = lane; k < SS; k += 32) {
                const float* Kr = &g_Kf[((size_t)b*SS + k)*HH];
                float s = 0.f;
                #pragma unroll 16
                for (int d = 0; d < HH; d++) s = fmaf(Q[d], Kr[d], s);
                s *= 0.125f;
                float t = (s > 0.f) ? s : expm1f(s);
                float mn = fmaxf(fm, t);
                fl = fl*__expf(fm - mn) + __expf(t - mn);
                fm = mn;
            }
            #pragma unroll
            for (int off = 16; off; off >>= 1) {
                float om = __shfl_xor_sync(0xffffffffu, fm, off);
                float ol = __shfl_xor_sync(0xffffffffu, fl, off);
                float mn = fmaxf(fm, om);
                fl = fl*__expf(fm - mn) + ol*__expf(om - mn);
                fm = mn;
            }
            S.so[warp*64 + lane] = 0.f;
            S.so[warp*64 + lane + 32] = 0.f;
            __syncwarp();
            for (int k = lane; k < SS; k += 32) {
                const float* Kr = &g_Kf[((size_t)b*SS + k)*HH];
                float s = 0.f;
                #pragma unroll 16
                for (int d = 0; d < HH; d++) s = fmaf(Q[d], Kr[d], s);
                s *= 0.125f;
                float t = (s > 0.f) ? s : expm1f(s);
                if (t > fm - 20.f) {
                    float w = __expf(t - fm);
                    const float* Vr = &g_Vf[((size_t)b*SS + k)*HH];
                    for (int h = 0; h < HH; h++)
                        atomicAdd(&S.so[warp*64 + h], w * Vr[h]);
                }
            }
            __syncwarp();
            l = fl;
            o.x = S.so[warp*64 + lane*2];
            o.y = S.so[warp*64 + lane*2 + 1];
        }

        float inv = (l > 0.f) ? (1.f / l) : 0.f;
        float2 gt = *(const float2*)&g_gate[b*HH + lane*2];
        float2 res = make_float2(o.x*inv*gt.x, o.y*inv*gt.y);
        *(float2*)&out[((size_t)b*SS + q0 + row)*HH + lane*2] = res;
    }
}

// ---------------- launch ----------------
extern "C" void kernel_launch(void* const* d_in, const int* in_sizes, int n_in,
                              void* d_out, int out_size) {
    int xi = 0;
    for (int i = 0; i < 4; i++) if (in_sizes[i] == BB*SS*DD) { xi = i; break; }
    const float* ptrs[3];
    int w = 0;
    for (int i = 0; i < 4; i++) if (i != xi) ptrs[w++] = (const float*)d_in[i];
    const float* x  = (const float*)d_in[xi];
    const float* Wq = ptrs[0];
    const float* Wk = ptrs[1];
    const float* Wv = ptrs[2];
    float* out = (float*)d_out;

    cudaFuncSetAttribute(attn_kernel, cudaFuncAttributeMaxDynamicSharedMemorySize,
                         (int)sizeof(Smem));

    qkv_kernel<<<RT/32, 192>>>(x, Wq, Wk, Wv);
    gate_kernel<<<BB*HH, 128>>>();
    attn_kernel<<<BB*(SS/TQ), 256, sizeof(Smem)>>>(out);
}

// round 15
// speedup vs baseline: 1.2198x; 1.1107x over previous
#include <cuda_runtime.h>
#include <cuda_bf16.h>
#include <math.h>
#include <stdint.h>

#define BB 8
#define SS 4096
#define DD 256
#define HH 64
#define RT (BB*SS)
#define TQ 64          // q rows per CTA (attn)
#define TK 256         // keys per tile
#define NT (SS/TK)     // 16 tiles
#define CAP 16

#define SQ_SCALE 0.75f
#define INV_SQ   1.33333333f
#define CONV     0.5625f     // SQ*SQ: s32 dot -> approx pre-scale

// ---------------- scratch ----------------
__device__ float g_Qf[RT*HH];
__device__ float g_Kf[RT*HH];
__device__ float g_Vf[RT*HH];
__device__ signed char g_K8[RT*HH];
__device__ float g_gate[BB*HH];

#define PACK2(dst, x) asm("mov.b64 %0, {%1, %1};" : "=l"(dst) : "r"(__float_as_uint(x)))
#define FMA2(acc, a, b) asm("fma.rn.f32x2 %0, %1, %2, %0;" : "+l"(acc) : "l"(a), "l"(b))
#define UNPACK2(lo, hi, v) asm("mov.b64 {%0, %1}, %2;" : "=r"(lo), "=r"(hi) : "l"(v))

#define CP16(dst, src)  asm volatile("cp.async.cg.shared.global [%0], [%1], 16;" :: "r"(dst), "l"(src) : "memory")
#define CP_COMMIT()     asm volatile("cp.async.commit_group;" ::: "memory")
#define CP_WAIT0()      asm volatile("cp.async.wait_group 0;" ::: "memory")
#define CP_WAIT1()      asm volatile("cp.async.wait_group 1;" ::: "memory")

__device__ __forceinline__ uint32_t smem_u32(const void* p) {
    uint32_t a;
    asm("{ .reg .u64 t; cvta.to.shared.u64 t, %1; cvt.u32.u64 %0, t; }" : "=r"(a) : "l"(p));
    return a;
}

__device__ __forceinline__ uint32_t pack4_s8(const float* q) {
    uint32_t r = 0;
    #pragma unroll
    for (int i = 0; i < 4; i++) {
        int v = __float2int_rn(q[i] * INV_SQ);
        v = v < -127 ? -127 : (v > 127 ? 127 : v);
        r |= ((uint32_t)(v & 255)) << (8*i);
    }
    return r;
}

// ---------------- kernel 1: fused QKV GEMM (FMA2, 16 rows/block for occupancy) ----
#define XSTR 260
__global__ __launch_bounds__(192) void qkv_kernel(
    const float* __restrict__ x, const float* __restrict__ Wq,
    const float* __restrict__ Wk, const float* __restrict__ Wv)
{
    __shared__ __align__(16) float xs[16*XSTR];
    int row0 = blockIdx.x * 16;
    int tid = threadIdx.x;

    for (int idx = tid; idx < 16*64; idx += 192) {
        int r = idx >> 6, k4 = (idx & 63) << 2;
        *(float4*)&xs[r*XSTR + k4] = *(const float4*)&x[(size_t)(row0 + r)*DD + k4];
    }
    __syncthreads();

    int m  = tid / 64;          // 0:Q 1:K 2:V
    int hq = (tid & 63) >> 2;   // 0..15
    int rg = tid & 3;           // rows rg, rg+4, rg+8, rg+12
    int h0 = hq * 4;
    const float* W = (m == 0) ? Wq : (m == 1) ? Wk : Wv;
    float* O = (m == 0) ? g_Qf : (m == 1) ? g_Kf : g_Vf;

    unsigned long long acc2[4][2];
    #pragma unroll
    for (int i = 0; i < 4; i++) { acc2[i][0] = 0ull; acc2[i][1] = 0ull; }

    #pragma unroll 2
    for (int k = 0; k < DD; k += 4) {
        ulonglong2 w[4];
        #pragma unroll
        for (int kk = 0; kk < 4; kk++)
            w[kk] = *(const ulonglong2*)&W[(size_t)(k+kk)*HH + h0];
        #pragma unroll
        for (int i = 0; i < 4; i++) {
            float4 xv = *(const float4*)&xs[(rg + 4*i)*XSTR + k];
            unsigned long long xp;
            PACK2(xp, xv.x); FMA2(acc2[i][0], w[0].x, xp); FMA2(acc2[i][1], w[0].y, xp);
            PACK2(xp, xv.y); FMA2(acc2[i][0], w[1].x, xp); FMA2(acc2[i][1], w[1].y, xp);
            PACK2(xp, xv.z); FMA2(acc2[i][0], w[2].x, xp); FMA2(acc2[i][1], w[2].y, xp);
            PACK2(xp, xv.w); FMA2(acc2[i][0], w[3].x, xp); FMA2(acc2[i][1], w[3].y, xp);
        }
    }

    #pragma unroll
    for (int i = 0; i < 4; i++) {
        int row = row0 + rg + 4*i;
        unsigned a, bq, cq, dq;
        UNPACK2(a, bq, acc2[i][0]);
        UNPACK2(cq, dq, acc2[i][1]);
        float4 o;
        o.x = __uint_as_float(a);  o.y = __uint_as_float(bq);
        o.z = __uint_as_float(cq); o.w = __uint_as_float(dq);
        *(float4*)&O[(size_t)row*HH + h0] = o;
        if (m == 1) {
            float t[4] = {o.x, o.y, o.z, o.w};
            *(uint32_t*)&g_K8[(size_t)row*HH + h0] = pack4_s8(t);
        }
    }
}

// ---------------- kernel 2: gate ----------------
__global__ __launch_bounds__(128) void gate_kernel() {
    int b = blockIdx.x >> 6;
    int h = blockIdx.x & 63;
    float s = 0.f;
    for (int i = threadIdx.x; i < SS; i += 128)
        s += g_Qf[((size_t)b*SS + i)*HH + h];
    __shared__ float red[128];
    red[threadIdx.x] = s;
    __syncthreads();
    for (int off = 64; off; off >>= 1) {
        if (threadIdx.x < off) red[threadIdx.x] += red[threadIdx.x + off];
        __syncthreads();
    }
    if (threadIdx.x == 0)
        g_gate[blockIdx.x] = 1.f / (1.f + expf(-red[0] * (1.f / (float)SS)));
}

// ---------------- kernel 3: two-sweep attention (int8 mma screen) ----------------
#define K8STR 80   // bytes per key in smem (conflict-free b-frag LDS)
struct __align__(16) Smem {
    float Qs[64*64];                    // 16384
    signed char K8[2][256*K8STR];       // 40960
    int rowtile[64*NT];                 // 4096 (s32 max, INT_MIN init)
    float Mpre[64];                     // approx pre-scale row max
    float thrpre[64];
    int thrq[64];                       // tile-qualify threshold in s32 space
    float cand_t[64*CAP];
    unsigned short cand_idx[64*CAP];
    unsigned cnt[64];
    int list[64];
    int nlist;
    int pad_;
    float so[8*64];
};

__global__ __launch_bounds__(256, 2) void attn_kernel(float* __restrict__ out) {
    extern __shared__ Smem smem[];
    Smem& S = smem[0];

    int tid = threadIdx.x;
    int b  = blockIdx.x >> 6;
    int q0 = (blockIdx.x & 63) * TQ;

    for (int i = tid; i < 64*NT; i += 256) S.rowtile[i] = (int)0x80000000;

    {
        int row = tid >> 2, qt = (tid & 3) * 16;
        const float* Qr = &g_Qf[((size_t)b*SS + q0 + row)*HH + qt];
        #pragma unroll
        for (int d4 = 0; d4 < 16; d4 += 4)
            *(float4*)&S.Qs[row*64 + qt + d4] = *(const float4*)&Qr[d4];
    }

    // preload K8 tile 0 into buf 0
    uint32_t kb_base = smem_u32(&S.K8[0][0]);
    {
        const signed char* Ksrc = &g_K8[((size_t)b*SS)*HH];
        #pragma unroll
        for (int j = 0; j < 4; j++) {
            int ch = tid + j*256;
            int key = ch >> 2, cc = ch & 3;
            CP16(kb_base + key*K8STR + cc*16, (const void*)(Ksrc + (size_t)key*HH + cc*16));
        }
        CP_COMMIT();
    }
    __syncthreads();

    int warp = tid >> 5, lane = tid & 31;
    int g = lane >> 2, tg = lane & 3;
    int wm = warp >> 1, wn = warp & 1;

    // ---- int8 A-fragments (m16n8k32), built once ----
    uint32_t afr[2][4];
    {
        int r0 = wm*16 + g, r1 = r0 + 8;
        #pragma unroll
        for (int kki = 0; kki < 2; kki++) {
            int kb0 = kki*32 + tg*4;
            afr[kki][0] = pack4_s8(&S.Qs[r0*64 + kb0]);
            afr[kki][1] = pack4_s8(&S.Qs[r1*64 + kb0]);
            afr[kki][2] = pack4_s8(&S.Qs[r0*64 + kb0 + 16]);
            afr[kki][3] = pack4_s8(&S.Qs[r1*64 + kb0 + 16]);
        }
    }

    // ================= sweep 1: s8 mma (K=32/instr), per-(row,tile) max ===========
    int buf = 0;
    for (int kt = 0; kt < NT; kt++) {
        if (kt + 1 < NT) {
            const signed char* Ksrc = &g_K8[((size_t)b*SS + (kt+1)*TK)*HH];
            uint32_t kb = smem_u32(&S.K8[buf ^ 1][0]);
            #pragma unroll
            for (int j = 0; j < 4; j++) {
                int ch = tid + j*256;
                int key = ch >> 2, cc = ch & 3;
                CP16(kb + key*K8STR + cc*16, (const void*)(Ksrc + (size_t)key*HH + cc*16));
            }
            CP_COMMIT();
            CP_WAIT1();
        } else {
            CP_WAIT0();
        }
        __syncthreads();

        const signed char* KB = &S.K8[buf][0];
        int acc[16][4];
        #pragma unroll
        for (int ni = 0; ni < 16; ni++)
            #pragma unroll
            for (int e = 0; e < 4; e++) acc[ni][e] = 0;

        #pragma unroll
        for (int kki = 0; kki < 2; kki++) {
            #pragma unroll
            for (int ni = 0; ni < 16; ni++) {
                int key = wn*128 + ni*8 + g;
                uint32_t b0 = *(const uint32_t*)&KB[key*K8STR + kki*32 + tg*4];
                uint32_t b1 = *(const uint32_t*)&KB[key*K8STR + kki*32 + 16 + tg*4];
                asm volatile(
                    "mma.sync.aligned.m16n8k32.row.col.s32.s8.s8.s32 "
                    "{%0,%1,%2,%3}, {%4,%5,%6,%7}, {%8,%9}, {%0,%1,%2,%3};"
                    : "+r"(acc[ni][0]), "+r"(acc[ni][1]),
                      "+r"(acc[ni][2]), "+r"(acc[ni][3])
                    : "r"(afr[kki][0]), "r"(afr[kki][1]), "r"(afr[kki][2]), "r"(afr[kki][3]),
                      "r"(b0), "r"(b1));
            }
        }

        int m0 = (int)0x80000000, m1 = (int)0x80000000;
        #pragma unroll
        for (int ni = 0; ni < 16; ni++) {
            m0 = max(m0, max(acc[ni][0], acc[ni][1]));
            m1 = max(m1, max(acc[ni][2], acc[ni][3]));
        }
        m0 = max(m0, __shfl_xor_sync(0xffffffffu, m0, 1));
        m0 = max(m0, __shfl_xor_sync(0xffffffffu, m0, 2));
        m1 = max(m1, __shfl_xor_sync(0xffffffffu, m1, 1));
        m1 = max(m1, __shfl_xor_sync(0xffffffffu, m1, 2));
        if (tg == 0) {
            atomicMax(&S.rowtile[(wm*16 + g    )*NT + kt], m0);
            atomicMax(&S.rowtile[(wm*16 + g + 8)*NT + kt], m1);
        }
        __syncthreads();
        buf ^= 1;
    }

    // thresholds (quantization error std ~39 pre-scale; margins 320/400)
    if (tid < 64) {
        int mk = (int)0x80000000;
        #pragma unroll
        for (int t = 0; t < NT; t++) mk = max(mk, S.rowtile[tid*NT + t]);
        float Mp = (float)mk * CONV;
        S.Mpre[tid]   = Mp;
        S.thrpre[tid] = Mp - 320.f;
        S.thrq[tid]   = (int)floorf((Mp - 400.f) * (1.f / CONV));
        S.cnt[tid] = (Mp < 400.f) ? (CAP + 1000u) : 0u;
    }
    __syncthreads();

    // ================= sweep 2: exact fp32 recompute on qualifying tiles ==========
    for (int kt = 0; kt < NT; kt++) {
        if (tid == 0) S.nlist = 0;
        __syncthreads();
        if (tid < 64 && S.rowtile[tid*NT + kt] > S.thrq[tid])
            S.list[atomicAdd(&S.nlist, 1)] = tid;
        __syncthreads();
        int n = S.nlist;
        if (n > 0) {
            float4 kr[16];
            const float* Kr = &g_Kf[((size_t)b*SS + kt*TK + tid)*HH];
            #pragma unroll
            for (int i = 0; i < 16; i++) kr[i] = *(const float4*)&Kr[i*4];
            for (int j = 0; j < n; j++) {
                int row = S.list[j];
                const float* Q = &S.Qs[row*64];
                float s0 = 0.f, s1 = 0.f, s2 = 0.f, s3 = 0.f;
                #pragma unroll
                for (int i = 0; i < 16; i++) {
                    s0 = fmaf(Q[i*4+0], kr[i].x, s0);
                    s1 = fmaf(Q[i*4+1], kr[i].y, s1);
                    s2 = fmaf(Q[i*4+2], kr[i].z, s2);
                    s3 = fmaf(Q[i*4+3], kr[i].w, s3);
                }
                float spre = (s0 + s1) + (s2 + s3);
                if (spre > S.thrpre[row]) {
                    float sc = spre * 0.125f;
                    float t = (sc > 0.f) ? sc : expm1f(sc);
                    unsigned slot = atomicAdd(&S.cnt[row], 1u);
                    if (slot < CAP) {
                        S.cand_t[row*CAP + slot] = t;
                        S.cand_idx[row*CAP + slot] = (unsigned short)(kt*TK + tid);
                    }
                }
            }
        }
        __syncthreads();
    }

    // ================= epilogue: detect + softmax + PV + gate =====================
    for (int rr = 0; rr < 8; rr++) {
        int row = warp*8 + rr;
        unsigned c = S.cnt[row];
        bool bad = (c > CAP) || (c == 0);
        float l = 0.f;
        float2 o = make_float2(0.f, 0.f);

        if (!bad) {
            float M = -3e38f;
            for (unsigned k = 0; k < c; k++) M = fmaxf(M, S.cand_t[row*CAP + k]);
            if (M < S.Mpre[row]*0.125f - 24.f) bad = true;   // consistency check
            if (!bad) {
                for (unsigned k = 0; k < c; k++) {
                    float w = __expf(S.cand_t[row*CAP + k] - M);
                    int idx = S.cand_idx[row*CAP + k];
                    float2 v = *(const float2*)&g_Vf[((size_t)b*SS + idx)*HH + lane*2];
                    l += w;
                    o.x += w * v.x;
                    o.y += w * v.y;
                }
            }
        }

        if (bad) {
            const float* Q = &S.Qs[row*64];
            float fm = -3e38f, fl = 0.f;
            for (int k = lane; k < SS; k += 32) {
                const float* Kr = &g_Kf[((size_t)b*SS + k)*HH];
                float s = 0.f;
                #pragma unroll 16
                for (int d = 0; d < HH; d++) s = fmaf(Q[d], Kr[d], s);
                s *= 0.125f;
                float t = (s > 0.f) ? s : expm1f(s);
                float mn = fmaxf(fm, t);
                fl = fl*__expf(fm - mn) + __expf(t - mn);
                fm = mn;
            }
            #pragma unroll
            for (int off = 16; off; off >>= 1) {
                float om = __shfl_xor_sync(0xffffffffu, fm, off);
                float ol = __shfl_xor_sync(0xffffffffu, fl, off);
                float mn = fmaxf(fm, om);
                fl = fl*__expf(fm - mn) + ol*__expf(om - mn);
                fm = mn;
            }
            S.so[warp*64 + lane] = 0.f;
            S.so[warp*64 + lane + 32] = 0.f;
            __syncwarp();
            for (int k = lane; k < SS; k += 32) {
                const float* Kr = &g_Kf[((size_t)b*SS + k)*HH];
                float s = 0.f;
                #pragma unroll 16
                for (int d = 0; d < HH; d++) s = fmaf(Q[d], Kr[d], s);
                s *= 0.125f;
                float t = (s > 0.f) ? s : expm1f(s);
                if (t > fm - 20.f) {
                    float w = __expf(t - fm);
                    const float* Vr = &g_Vf[((size_t)b*SS + k)*HH];
                    for (int h = 0; h < HH; h++)
                        atomicAdd(&S.so[warp*64 + h], w * Vr[h]);
                }
            }
            __syncwarp();
            l = fl;
            o.x = S.so[warp*64 + lane*2];
            o.y = S.so[warp*64 + lane*2 + 1];
        }

        float inv = (l > 0.f) ? (1.f / l) : 0.f;
        float2 gt = *(const float2*)&g_gate[b*HH + lane*2];
        float2 res = make_float2(o.x*inv*gt.x, o.y*inv*gt.y);
        *(float2*)&out[((size_t)b*SS + q0 + row)*HH + lane*2] = res;
    }
}

// ---------------- launch ----------------
extern "C" void kernel_launch(void* const* d_in, const int* in_sizes, int n_in,
                              void* d_out, int out_size) {
    int xi = 0;
    for (int i = 0; i < 4; i++) if (in_sizes[i] == BB*SS*DD) { xi = i; break; }
    const float* ptrs[3];
    int w = 0;
    for (int i = 0; i < 4; i++) if (i != xi) ptrs[w++] = (const float*)d_in[i];
    const float* x  = (const float*)d_in[xi];
    const float* Wq = ptrs[0];
    const float* Wk = ptrs[1];
    const float* Wv = ptrs[2];
    float* out = (float*)d_out;

    cudaFuncSetAttribute(attn_kernel, cudaFuncAttributeMaxDynamicSharedMemorySize,
                         (int)sizeof(Smem));

    qkv_kernel<<<RT/16, 192>>>(x, Wq, Wk, Wv);
    gate_kernel<<<BB*HH, 128>>>();
    attn_kernel<<<BB*(SS/TQ), 256, sizeof(Smem)>>>(out);
}